// round 2
// baseline (speedup 1.0000x reference)
#include <cuda_runtime.h>

#define NB 32
#define C  64
#define T  64
#define V  128
#define KK 128   // RED*T

// Scratch (allocation-free rule: __device__ globals)
__device__ float g_xf[(size_t)NB*C*T*V];     // 67 MB
__device__ float g_a [(size_t)NB*KK*V];      // 2 MB
__device__ float g_b [(size_t)NB*KK*V];      // 2 MB
__device__ float g_xm[(size_t)NB*T*V*V];     // 134 MB

union f2u { float2 f; unsigned long long u; };

__device__ __forceinline__ unsigned long long pack2(float x, float y){
    f2u t; t.f = make_float2(x, y); return t.u;
}
__device__ __forceinline__ unsigned long long fma2(unsigned long long a,
                                                   unsigned long long b,
                                                   unsigned long long c){
    unsigned long long d;
    asm("fma.rn.f32x2 %0, %1, %2, %3;" : "=l"(d) : "l"(a), "l"(b), "l"(c));
    return d;
}
__device__ __forceinline__ float tanh_fast(float x){
    float y; asm("tanh.approx.f32 %0, %1;" : "=f"(y) : "f"(x)); return y;
}

// ---------------------------------------------------------------------------
// Kernel 1: xf = Wf@x + bf  (per (n,t): 64x128 = [64x64]@[64x128])
//           a[n, r*T+t, v] = Wm1@x + bm1 ; b likewise with Wm2
// grid (T, NB), 256 threads
// ---------------------------------------------------------------------------
__global__ __launch_bounds__(256) void k1(
    const float* __restrict__ x,  const float* __restrict__ Wf,
    const float* __restrict__ bf, const float* __restrict__ Wm1,
    const float* __restrict__ bm1,const float* __restrict__ Wm2,
    const float* __restrict__ bm2)
{
    __shared__ float xs[32][V];      // 16 KB  (c-chunk of x[n,:,t,:])
    __shared__ float wfs[C][32];     // 8 KB   (Wf[o][c-chunk])
    __shared__ float wm1s[2][C];
    __shared__ float wm2s[2][C];

    const int t = blockIdx.x, n = blockIdx.y;
    const int tid = threadIdx.x;

    if (tid < 128){ ((float*)wm1s)[tid] = Wm1[tid]; ((float*)wm2s)[tid] = Wm2[tid]; }

    const int o0 = (tid >> 4) << 2;   // 16 groups of 4 output channels
    const int v0 = (tid & 15) << 3;   // 16 groups of 8 v

    unsigned long long acc[4][4];
#pragma unroll
    for (int i = 0; i < 4; i++){
        float bb = bf[o0 + i];
        unsigned long long p = pack2(bb, bb);
#pragma unroll
        for (int j = 0; j < 4; j++) acc[i][j] = p;
    }

    const int rr = tid >> 7;          // 0..1
    const int vv = tid & 127;         // 0..127
    float aacc = bm1[rr], bacc = bm2[rr];

#pragma unroll
    for (int ch = 0; ch < 2; ch++){
        __syncthreads();
        // load x chunk: rows c = ch*32 .. ch*32+31, each row 128 contiguous floats
#pragma unroll
        for (int i = 0; i < 4; i++){
            int idx = i*256 + tid; int c = idx >> 5; int p = idx & 31;
            ((float4*)xs)[c*32 + p] =
                *(const float4*)(x + (((size_t)n*C + ch*32 + c)*T + t)*V + p*4);
        }
        // load Wf chunk
#pragma unroll
        for (int i = 0; i < 2; i++){
            int idx = i*256 + tid; int o = idx >> 3; int p = idx & 7;
            ((float4*)wfs)[o*8 + p] =
                *(const float4*)(Wf + (size_t)o*64 + ch*32 + p*4);
        }
        __syncthreads();

#pragma unroll 4
        for (int cc = 0; cc < 32; cc++){
            float4 xa = *(const float4*)&xs[cc][v0];
            float4 xb = *(const float4*)&xs[cc][v0 + 4];
            unsigned long long xv0 = pack2(xa.x, xa.y);
            unsigned long long xv1 = pack2(xa.z, xa.w);
            unsigned long long xv2 = pack2(xb.x, xb.y);
            unsigned long long xv3 = pack2(xb.z, xb.w);
#pragma unroll
            for (int i = 0; i < 4; i++){
                float wsc = wfs[o0 + i][cc];
                unsigned long long wb = pack2(wsc, wsc);
                acc[i][0] = fma2(wb, xv0, acc[i][0]);
                acc[i][1] = fma2(wb, xv1, acc[i][1]);
                acc[i][2] = fma2(wb, xv2, acc[i][2]);
                acc[i][3] = fma2(wb, xv3, acc[i][3]);
            }
            float xval = xs[cc][vv];
            aacc = fmaf(wm1s[rr][ch*32 + cc], xval, aacc);
            bacc = fmaf(wm2s[rr][ch*32 + cc], xval, bacc);
        }
    }

    // store xf tile
#pragma unroll
    for (int i = 0; i < 4; i++){
        f2u u0, u1, u2, u3;
        u0.u = acc[i][0]; u1.u = acc[i][1]; u2.u = acc[i][2]; u3.u = acc[i][3];
        float* dst = g_xf + (((size_t)n*C + o0 + i)*T + t)*V + v0;
        *(float4*)(dst    ) = make_float4(u0.f.x, u0.f.y, u1.f.x, u1.f.y);
        *(float4*)(dst + 4) = make_float4(u2.f.x, u2.f.y, u3.f.x, u3.f.y);
    }
    // store a/b: a[n][rr*T + t][vv]
    g_a[((size_t)n*KK + rr*T + t)*V + vv] = aacc;
    g_b[((size_t)n*KK + rr*T + t)*V + vv] = bacc;
}

// ---------------------------------------------------------------------------
// Kernel 2: xm[n,t,v,w] = sum_k Wrm[t,k]*tanh(a[n,k,v]-b[n,k,w]) + brm[t] + A[t,v,w]
// grid (V/16, V/16, NB), 256 threads; thread = one (v,w), 64 t-accumulators (packed)
// ---------------------------------------------------------------------------
__global__ __launch_bounds__(256, 2) void k2(
    const float* __restrict__ Wrm, const float* __restrict__ brm,
    const float* __restrict__ A)
{
    __shared__ float as_[KK][16];    // 8 KB
    __shared__ float bs_[KK][16];    // 8 KB
    __shared__ float wts[KK][C];     // 32 KB, wts[k][t] = Wrm[t][k]

    const int vt = blockIdx.x, wt = blockIdx.y, n = blockIdx.z;
    const int tid = threadIdx.x;
    const int vi = tid >> 4, wi = tid & 15;

#pragma unroll
    for (int i = 0; i < 8; i++){
        int idx = i*256 + tid; int k = idx >> 4; int p = idx & 15;
        as_[k][p] = g_a[((size_t)n*KK + k)*V + vt*16 + p];
        bs_[k][p] = g_b[((size_t)n*KK + k)*V + wt*16 + p];
    }
#pragma unroll
    for (int i = 0; i < 32; i++){
        int idx = i*256 + tid; int k = idx >> 6; int tt = idx & 63;
        wts[k][tt] = Wrm[(size_t)tt*KK + k];
    }

    unsigned long long acc[32];
#pragma unroll
    for (int t2 = 0; t2 < 32; t2++) acc[t2] = pack2(brm[2*t2], brm[2*t2 + 1]);

    __syncthreads();

    const int v = vt*16 + vi, w = wt*16 + wi;

#pragma unroll 2
    for (int k = 0; k < KK; k++){
        float d = tanh_fast(as_[k][vi] - bs_[k][wi]);
        unsigned long long dd = pack2(d, d);
        const float4* w4 = (const float4*)&wts[k][0];
#pragma unroll
        for (int t4 = 0; t4 < 16; t4++){
            float4 wv = w4[t4];
            acc[2*t4    ] = fma2(pack2(wv.x, wv.y), dd, acc[2*t4    ]);
            acc[2*t4 + 1] = fma2(pack2(wv.z, wv.w), dd, acc[2*t4 + 1]);
        }
    }

    float* xmb = g_xm + (size_t)n*T*V*V;
#pragma unroll
    for (int t2 = 0; t2 < 32; t2++){
        f2u u; u.u = acc[t2];
        int t0 = 2*t2, t1 = t0 + 1;
        xmb[((size_t)t0*V + v)*V + w] = u.f.x + A[((size_t)t0*V + v)*V + w];
        xmb[((size_t)t1*V + v)*V + w] = u.f.y + A[((size_t)t1*V + v)*V + w];
    }
}

// ---------------------------------------------------------------------------
// Kernel 3: out[n,c,t,w] = sum_v xf[n,c,t,v] * xm[n,t,v,w]
// grid (T, NB), 256 threads; per block: [64x128] @ [128x128]
// ---------------------------------------------------------------------------
__global__ __launch_bounds__(256) void k3(float* __restrict__ out)
{
    __shared__ float xfs[C][64];     // 16 KB (v-chunk of xf)
    __shared__ float xms[64][V];     // 32 KB (v-chunk of xm)

    const int t = blockIdx.x, n = blockIdx.y;
    const int tid = threadIdx.x;
    const int o0 = (tid >> 4) << 2, w0 = (tid & 15) << 3;

    unsigned long long acc[4][4];
#pragma unroll
    for (int i = 0; i < 4; i++)
#pragma unroll
        for (int j = 0; j < 4; j++) acc[i][j] = 0ull;

#pragma unroll
    for (int vc = 0; vc < 2; vc++){
        __syncthreads();
#pragma unroll
        for (int i = 0; i < 4; i++){
            int idx = i*256 + tid; int c = idx >> 4; int p = idx & 15;
            ((float4*)xfs)[c*16 + p] =
                *(const float4*)(g_xf + (((size_t)n*C + c)*T + t)*V + vc*64 + p*4);
        }
#pragma unroll
        for (int i = 0; i < 8; i++){
            int idx = i*256 + tid; int vv = idx >> 5; int p = idx & 31;
            ((float4*)xms)[vv*32 + p] =
                *(const float4*)(g_xm + (((size_t)n*T + t)*V + vc*64 + vv)*V + p*4);
        }
        __syncthreads();

#pragma unroll 2
        for (int vv = 0; vv < 64; vv++){
            float4 xa = *(const float4*)&xms[vv][w0];
            float4 xb = *(const float4*)&xms[vv][w0 + 4];
            unsigned long long xv0 = pack2(xa.x, xa.y);
            unsigned long long xv1 = pack2(xa.z, xa.w);
            unsigned long long xv2 = pack2(xb.x, xb.y);
            unsigned long long xv3 = pack2(xb.z, xb.w);
#pragma unroll
            for (int i = 0; i < 4; i++){
                float f = xfs[o0 + i][vv];
                unsigned long long ff = pack2(f, f);
                acc[i][0] = fma2(ff, xv0, acc[i][0]);
                acc[i][1] = fma2(ff, xv1, acc[i][1]);
                acc[i][2] = fma2(ff, xv2, acc[i][2]);
                acc[i][3] = fma2(ff, xv3, acc[i][3]);
            }
        }
    }

#pragma unroll
    for (int i = 0; i < 4; i++){
        f2u u0, u1, u2, u3;
        u0.u = acc[i][0]; u1.u = acc[i][1]; u2.u = acc[i][2]; u3.u = acc[i][3];
        float* dst = out + (((size_t)n*C + o0 + i)*T + t)*V + w0;
        *(float4*)(dst    ) = make_float4(u0.f.x, u0.f.y, u1.f.x, u1.f.y);
        *(float4*)(dst + 4) = make_float4(u2.f.x, u2.f.y, u3.f.x, u3.f.y);
    }
}

extern "C" void kernel_launch(void* const* d_in, const int* in_sizes, int n_in,
                              void* d_out, int out_size)
{
    const float* x   = (const float*)d_in[0];
    const float* A   = (const float*)d_in[1];
    const float* Wf  = (const float*)d_in[2];
    const float* bf  = (const float*)d_in[3];
    const float* Wm1 = (const float*)d_in[4];
    const float* bm1 = (const float*)d_in[5];
    const float* Wm2 = (const float*)d_in[6];
    const float* bm2 = (const float*)d_in[7];
    const float* Wrm = (const float*)d_in[8];
    const float* brm = (const float*)d_in[9];
    float* out = (float*)d_out;

    k1<<<dim3(T, NB), 256>>>(x, Wf, bf, Wm1, bm1, Wm2, bm2);
    k2<<<dim3(V/16, V/16, NB), 256>>>(Wrm, brm, A);
    k3<<<dim3(T, NB), 256>>>(out);
}

// round 3
// speedup vs baseline: 1.0214x; 1.0214x over previous
#include <cuda_runtime.h>
#include <cuda_fp16.h>

#define NB 32
#define C  64
#define T  64
#define V  128
#define KK 128   // RED*T

// Scratch (allocation-free rule: __device__ globals)
__device__ __half g_xf_h[(size_t)NB*C*T*V];     // 34 MB
__device__ float  g_a  [(size_t)NB*KK*V];       // 2 MB
__device__ float  g_b  [(size_t)NB*KK*V];       // 2 MB
__device__ __half g_xm_h[(size_t)NB*T*V*V];     // 67 MB

union f2u { float2 f; unsigned long long u; };

__device__ __forceinline__ unsigned long long pack2(float x, float y){
    f2u t; t.f = make_float2(x, y); return t.u;
}
__device__ __forceinline__ unsigned long long fma2(unsigned long long a,
                                                   unsigned long long b,
                                                   unsigned long long c){
    unsigned long long d;
    asm("fma.rn.f32x2 %0, %1, %2, %3;" : "=l"(d) : "l"(a), "l"(b), "l"(c));
    return d;
}
__device__ __forceinline__ float tanh_fast(float x){
    float y; asm("tanh.approx.f32 %0, %1;" : "=f"(y) : "f"(x)); return y;
}
__device__ __forceinline__ void h8_to_f8(uint4 r, float* dst){
    const __half2* h = (const __half2*)&r;
    float2 f0 = __half22float2(h[0]);
    float2 f1 = __half22float2(h[1]);
    float2 f2 = __half22float2(h[2]);
    float2 f3 = __half22float2(h[3]);
    dst[0]=f0.x; dst[1]=f0.y; dst[2]=f1.x; dst[3]=f1.y;
    dst[4]=f2.x; dst[5]=f2.y; dst[6]=f3.x; dst[7]=f3.y;
}

// ---------------------------------------------------------------------------
// Kernel 1: xf = Wf@x + bf  (per (n,t): 64x128 = [64x64]@[64x128]) -> fp16
//           a[n, r*T+t, v] = Wm1@x + bm1 ; b likewise with Wm2 (fp32)
// grid (T, NB), 256 threads
// ---------------------------------------------------------------------------
__global__ __launch_bounds__(256) void k1(
    const float* __restrict__ x,  const float* __restrict__ Wf,
    const float* __restrict__ bf, const float* __restrict__ Wm1,
    const float* __restrict__ bm1,const float* __restrict__ Wm2,
    const float* __restrict__ bm2)
{
    __shared__ float xs[32][V];       // 16 KB  (c-chunk of x[n,:,t,:])
    __shared__ float wfsT[32][68];    // transposed Wf chunk: wfsT[cc][o], padded
    __shared__ float wm1s[2][C];
    __shared__ float wm2s[2][C];

    const int t = blockIdx.x, n = blockIdx.y;
    const int tid = threadIdx.x;

    if (tid < 128){ ((float*)wm1s)[tid] = Wm1[tid]; ((float*)wm2s)[tid] = Wm2[tid]; }

    const int o0 = (tid >> 4) << 2;   // 16 groups of 4 output channels
    const int v0 = (tid & 15) << 3;   // 16 groups of 8 v

    unsigned long long acc[4][4];
#pragma unroll
    for (int i = 0; i < 4; i++){
        float bb = bf[o0 + i];
        unsigned long long p = pack2(bb, bb);
#pragma unroll
        for (int j = 0; j < 4; j++) acc[i][j] = p;
    }

    const int rr = tid >> 7;          // 0..1
    const int vv = tid & 127;         // 0..127
    float aacc = bm1[rr], bacc = bm2[rr];

#pragma unroll
    for (int ch = 0; ch < 2; ch++){
        __syncthreads();
        // load x chunk: rows c = ch*32 .. ch*32+31, each row 128 contiguous floats
#pragma unroll
        for (int i = 0; i < 4; i++){
            int idx = i*256 + tid; int c = idx >> 5; int p = idx & 31;
            ((float4*)xs)[c*32 + p] =
                *(const float4*)(x + (((size_t)n*C + ch*32 + c)*T + t)*V + p*4);
        }
        // load Wf chunk transposed: wfsT[cc][o] = Wf[o][ch*32+cc]
#pragma unroll
        for (int i = 0; i < 8; i++){
            int idx = i*256 + tid; int o = idx >> 5; int cc = idx & 31;
            wfsT[cc][o] = Wf[(size_t)o*64 + ch*32 + cc];
        }
        __syncthreads();

#pragma unroll 4
        for (int cc = 0; cc < 32; cc++){
            float4 xa = *(const float4*)&xs[cc][v0];
            float4 xb = *(const float4*)&xs[cc][v0 + 4];
            unsigned long long xv0 = pack2(xa.x, xa.y);
            unsigned long long xv1 = pack2(xa.z, xa.w);
            unsigned long long xv2 = pack2(xb.x, xb.y);
            unsigned long long xv3 = pack2(xb.z, xb.w);
            float4 wv = *(const float4*)&wfsT[cc][o0];
            float wq[4] = {wv.x, wv.y, wv.z, wv.w};
#pragma unroll
            for (int i = 0; i < 4; i++){
                unsigned long long wb = pack2(wq[i], wq[i]);
                acc[i][0] = fma2(wb, xv0, acc[i][0]);
                acc[i][1] = fma2(wb, xv1, acc[i][1]);
                acc[i][2] = fma2(wb, xv2, acc[i][2]);
                acc[i][3] = fma2(wb, xv3, acc[i][3]);
            }
            float xval = xs[cc][vv];
            aacc = fmaf(wm1s[rr][ch*32 + cc], xval, aacc);
            bacc = fmaf(wm2s[rr][ch*32 + cc], xval, bacc);
        }
    }

    // store xf tile as fp16
#pragma unroll
    for (int i = 0; i < 4; i++){
        f2u u0, u1, u2, u3;
        u0.u = acc[i][0]; u1.u = acc[i][1]; u2.u = acc[i][2]; u3.u = acc[i][3];
        uint4 packed;
        __half2 h0 = __floats2half2_rn(u0.f.x, u0.f.y);
        __half2 h1 = __floats2half2_rn(u1.f.x, u1.f.y);
        __half2 h2 = __floats2half2_rn(u2.f.x, u2.f.y);
        __half2 h3 = __floats2half2_rn(u3.f.x, u3.f.y);
        packed.x = *(unsigned*)&h0; packed.y = *(unsigned*)&h1;
        packed.z = *(unsigned*)&h2; packed.w = *(unsigned*)&h3;
        *(uint4*)(g_xf_h + (((size_t)n*C + o0 + i)*T + t)*V + v0) = packed;
    }
    g_a[((size_t)n*KK + rr*T + t)*V + vv] = aacc;
    g_b[((size_t)n*KK + rr*T + t)*V + vv] = bacc;
}

// ---------------------------------------------------------------------------
// Kernel 2: xm[n,t,v,w] = sum_k Wrm[t,k]*tanh(a[n,k,v]-b[n,k,w]) + brm[t] + A[t,v,w]
// grid (V/16, V/16, NB), 256 threads; thread = one (v,w), 64 t-accumulators
// stores fp16
// ---------------------------------------------------------------------------
__global__ __launch_bounds__(256, 2) void k2(
    const float* __restrict__ Wrm, const float* __restrict__ brm,
    const float* __restrict__ A)
{
    __shared__ float as_[KK][16];    // 8 KB
    __shared__ float bs_[KK][16];    // 8 KB
    __shared__ float wts[KK][C];     // 32 KB, wts[k][t] = Wrm[t][k]

    const int vt = blockIdx.x, wt = blockIdx.y, n = blockIdx.z;
    const int tid = threadIdx.x;
    const int vi = tid >> 4, wi = tid & 15;

#pragma unroll
    for (int i = 0; i < 8; i++){
        int idx = i*256 + tid; int k = idx >> 4; int p = idx & 15;
        as_[k][p] = g_a[((size_t)n*KK + k)*V + vt*16 + p];
        bs_[k][p] = g_b[((size_t)n*KK + k)*V + wt*16 + p];
    }
#pragma unroll
    for (int i = 0; i < 32; i++){
        int idx = i*256 + tid; int k = idx >> 6; int tt = idx & 63;
        wts[k][tt] = Wrm[(size_t)tt*KK + k];
    }

    unsigned long long acc[32];
#pragma unroll
    for (int t2 = 0; t2 < 32; t2++) acc[t2] = pack2(brm[2*t2], brm[2*t2 + 1]);

    __syncthreads();

    const int v = vt*16 + vi, w = wt*16 + wi;

#pragma unroll 2
    for (int k = 0; k < KK; k++){
        float d = tanh_fast(as_[k][vi] - bs_[k][wi]);
        unsigned long long dd = pack2(d, d);
        const float4* w4 = (const float4*)&wts[k][0];
#pragma unroll
        for (int t4 = 0; t4 < 16; t4++){
            float4 wv = w4[t4];
            acc[2*t4    ] = fma2(pack2(wv.x, wv.y), dd, acc[2*t4    ]);
            acc[2*t4 + 1] = fma2(pack2(wv.z, wv.w), dd, acc[2*t4 + 1]);
        }
    }

    __half* xmb = g_xm_h + (size_t)n*T*V*V;
#pragma unroll
    for (int t2 = 0; t2 < 32; t2++){
        f2u u; u.u = acc[t2];
        int t0 = 2*t2, t1 = t0 + 1;
        xmb[((size_t)t0*V + v)*V + w] = __float2half(u.f.x + A[((size_t)t0*V + v)*V + w]);
        xmb[((size_t)t1*V + v)*V + w] = __float2half(u.f.y + A[((size_t)t1*V + v)*V + w]);
    }
}

// ---------------------------------------------------------------------------
// Kernel 3: out[n,c,t,w] = sum_v xf[n,c,t,v] * xm[n,t,v,w]
// grid (T, NB), 256 threads; per block: [64x128] @ [128x128]; fp16 in, fp32 out
// ---------------------------------------------------------------------------
__global__ __launch_bounds__(256) void k3(float* __restrict__ out)
{
    __shared__ float xfs[C][64];     // 16 KB (v-chunk of xf)
    __shared__ float xms[64][V];     // 32 KB (v-chunk of xm)

    const int t = blockIdx.x, n = blockIdx.y;
    const int tid = threadIdx.x;
    const int o0 = (tid >> 4) << 2, w0 = (tid & 15) << 3;

    unsigned long long acc[4][4];
#pragma unroll
    for (int i = 0; i < 4; i++)
#pragma unroll
        for (int j = 0; j < 4; j++) acc[i][j] = 0ull;

#pragma unroll
    for (int vc = 0; vc < 2; vc++){
        __syncthreads();
        // xf chunk: 64 c x 64 v halves
#pragma unroll
        for (int i = 0; i < 2; i++){
            int idx = i*256 + tid; int c = idx >> 3; int p = idx & 7;
            uint4 raw = *(const uint4*)(g_xf_h + (((size_t)n*C + c)*T + t)*V + vc*64 + p*8);
            h8_to_f8(raw, &xfs[c][p*8]);
        }
        // xm chunk: 64 v x 128 w halves
#pragma unroll
        for (int i = 0; i < 4; i++){
            int idx = i*256 + tid; int vv = idx >> 4; int p = idx & 15;
            uint4 raw = *(const uint4*)(g_xm_h + (((size_t)n*T + t)*V + vc*64 + vv)*V + p*8);
            h8_to_f8(raw, &xms[vv][p*8]);
        }
        __syncthreads();

#pragma unroll 2
        for (int vv = 0; vv < 64; vv++){
            float4 xa = *(const float4*)&xms[vv][w0];
            float4 xb = *(const float4*)&xms[vv][w0 + 4];
            unsigned long long xv0 = pack2(xa.x, xa.y);
            unsigned long long xv1 = pack2(xa.z, xa.w);
            unsigned long long xv2 = pack2(xb.x, xb.y);
            unsigned long long xv3 = pack2(xb.z, xb.w);
#pragma unroll
            for (int i = 0; i < 4; i++){
                float f = xfs[o0 + i][vv];
                unsigned long long ff = pack2(f, f);
                acc[i][0] = fma2(ff, xv0, acc[i][0]);
                acc[i][1] = fma2(ff, xv1, acc[i][1]);
                acc[i][2] = fma2(ff, xv2, acc[i][2]);
                acc[i][3] = fma2(ff, xv3, acc[i][3]);
            }
        }
    }

#pragma unroll
    for (int i = 0; i < 4; i++){
        f2u u0, u1, u2, u3;
        u0.u = acc[i][0]; u1.u = acc[i][1]; u2.u = acc[i][2]; u3.u = acc[i][3];
        float* dst = out + (((size_t)n*C + o0 + i)*T + t)*V + w0;
        *(float4*)(dst    ) = make_float4(u0.f.x, u0.f.y, u1.f.x, u1.f.y);
        *(float4*)(dst + 4) = make_float4(u2.f.x, u2.f.y, u3.f.x, u3.f.y);
    }
}

extern "C" void kernel_launch(void* const* d_in, const int* in_sizes, int n_in,
                              void* d_out, int out_size)
{
    const float* x   = (const float*)d_in[0];
    const float* A   = (const float*)d_in[1];
    const float* Wf  = (const float*)d_in[2];
    const float* bf  = (const float*)d_in[3];
    const float* Wm1 = (const float*)d_in[4];
    const float* bm1 = (const float*)d_in[5];
    const float* Wm2 = (const float*)d_in[6];
    const float* bm2 = (const float*)d_in[7];
    const float* Wrm = (const float*)d_in[8];
    const float* brm = (const float*)d_in[9];
    float* out = (float*)d_out;

    k1<<<dim3(T, NB), 256>>>(x, Wf, bf, Wm1, bm1, Wm2, bm2);
    k2<<<dim3(V/16, V/16, NB), 256>>>(Wrm, brm, A);
    k3<<<dim3(T, NB), 256>>>(out);
}

// round 4
// speedup vs baseline: 2.7615x; 2.7036x over previous
#include <cuda_runtime.h>
#include <cuda_fp16.h>

#define NB 32
#define C  64
#define T  64
#define V  128
#define KK 128   // RED*T

// Scratch (allocation-free rule: __device__ globals)
__device__ __half g_xf_h[(size_t)NB*C*T*V];     // 34 MB
__device__ float  g_a  [(size_t)NB*KK*V];       // 2 MB
__device__ float  g_b  [(size_t)NB*KK*V];       // 2 MB
__device__ __half g_xm_h[(size_t)NB*T*V*V];     // 67 MB

union f2u { float2 f; unsigned long long u; };

__device__ __forceinline__ unsigned long long pack2(float x, float y){
    f2u t; t.f = make_float2(x, y); return t.u;
}
__device__ __forceinline__ unsigned long long fma2(unsigned long long a,
                                                   unsigned long long b,
                                                   unsigned long long c){
    unsigned long long d;
    asm("fma.rn.f32x2 %0, %1, %2, %3;" : "=l"(d) : "l"(a), "l"(b), "l"(c));
    return d;
}
__device__ __forceinline__ float tanh_fast(float x){
    float y; asm("tanh.approx.f32 %0, %1;" : "=f"(y) : "f"(x)); return y;
}

__device__ __forceinline__ unsigned smem_u32(const void* p){
    return (unsigned)__cvta_generic_to_shared(p);
}
__device__ __forceinline__ void ldm_x4(unsigned addr, unsigned& r0, unsigned& r1,
                                       unsigned& r2, unsigned& r3){
    asm volatile("ldmatrix.sync.aligned.m8n8.x4.shared.b16 {%0,%1,%2,%3}, [%4];"
                 : "=r"(r0), "=r"(r1), "=r"(r2), "=r"(r3) : "r"(addr));
}
__device__ __forceinline__ void ldm_x2t(unsigned addr, unsigned& r0, unsigned& r1){
    asm volatile("ldmatrix.sync.aligned.m8n8.x2.trans.shared.b16 {%0,%1}, [%2];"
                 : "=r"(r0), "=r"(r1) : "r"(addr));
}
__device__ __forceinline__ void mma16816(float* c, const unsigned* a, const unsigned* b){
    asm volatile("mma.sync.aligned.m16n8k16.row.col.f32.f16.f16.f32 "
                 "{%0,%1,%2,%3}, {%4,%5,%6,%7}, {%8,%9}, {%0,%1,%2,%3};"
                 : "+f"(c[0]), "+f"(c[1]), "+f"(c[2]), "+f"(c[3])
                 : "r"(a[0]), "r"(a[1]), "r"(a[2]), "r"(a[3]),
                   "r"(b[0]), "r"(b[1]));
}

// ---------------------------------------------------------------------------
// Kernel 1: xf = Wf@x + bf -> fp16 ;  a/b = Wm@x + bm (fp32). grid (T, NB)
// ---------------------------------------------------------------------------
__global__ __launch_bounds__(256) void k1(
    const float* __restrict__ x,  const float* __restrict__ Wf,
    const float* __restrict__ bf, const float* __restrict__ Wm1,
    const float* __restrict__ bm1,const float* __restrict__ Wm2,
    const float* __restrict__ bm2)
{
    __shared__ float xs[32][V];
    __shared__ float wfsT[32][68];
    __shared__ float wm1s[2][C];
    __shared__ float wm2s[2][C];

    const int t = blockIdx.x, n = blockIdx.y;
    const int tid = threadIdx.x;

    if (tid < 128){ ((float*)wm1s)[tid] = Wm1[tid]; ((float*)wm2s)[tid] = Wm2[tid]; }

    const int o0 = (tid >> 4) << 2;
    const int v0 = (tid & 15) << 3;

    unsigned long long acc[4][4];
#pragma unroll
    for (int i = 0; i < 4; i++){
        float bb = bf[o0 + i];
        unsigned long long p = pack2(bb, bb);
#pragma unroll
        for (int j = 0; j < 4; j++) acc[i][j] = p;
    }

    const int rr = tid >> 7;
    const int vv = tid & 127;
    float aacc = bm1[rr], bacc = bm2[rr];

#pragma unroll
    for (int ch = 0; ch < 2; ch++){
        __syncthreads();
#pragma unroll
        for (int i = 0; i < 4; i++){
            int idx = i*256 + tid; int c = idx >> 5; int p = idx & 31;
            ((float4*)xs)[c*32 + p] =
                *(const float4*)(x + (((size_t)n*C + ch*32 + c)*T + t)*V + p*4);
        }
#pragma unroll
        for (int i = 0; i < 8; i++){
            int idx = i*256 + tid; int o = idx >> 5; int cc = idx & 31;
            wfsT[cc][o] = Wf[(size_t)o*64 + ch*32 + cc];
        }
        __syncthreads();

#pragma unroll 4
        for (int cc = 0; cc < 32; cc++){
            float4 xa = *(const float4*)&xs[cc][v0];
            float4 xb = *(const float4*)&xs[cc][v0 + 4];
            unsigned long long xv0 = pack2(xa.x, xa.y);
            unsigned long long xv1 = pack2(xa.z, xa.w);
            unsigned long long xv2 = pack2(xb.x, xb.y);
            unsigned long long xv3 = pack2(xb.z, xb.w);
            float4 wv = *(const float4*)&wfsT[cc][o0];
            float wq[4] = {wv.x, wv.y, wv.z, wv.w};
#pragma unroll
            for (int i = 0; i < 4; i++){
                unsigned long long wb = pack2(wq[i], wq[i]);
                acc[i][0] = fma2(wb, xv0, acc[i][0]);
                acc[i][1] = fma2(wb, xv1, acc[i][1]);
                acc[i][2] = fma2(wb, xv2, acc[i][2]);
                acc[i][3] = fma2(wb, xv3, acc[i][3]);
            }
            float xval = xs[cc][vv];
            aacc = fmaf(wm1s[rr][ch*32 + cc], xval, aacc);
            bacc = fmaf(wm2s[rr][ch*32 + cc], xval, bacc);
        }
    }

#pragma unroll
    for (int i = 0; i < 4; i++){
        f2u u0, u1, u2, u3;
        u0.u = acc[i][0]; u1.u = acc[i][1]; u2.u = acc[i][2]; u3.u = acc[i][3];
        uint4 packed;
        __half2 h0 = __floats2half2_rn(u0.f.x, u0.f.y);
        __half2 h1 = __floats2half2_rn(u1.f.x, u1.f.y);
        __half2 h2 = __floats2half2_rn(u2.f.x, u2.f.y);
        __half2 h3 = __floats2half2_rn(u3.f.x, u3.f.y);
        packed.x = *(unsigned*)&h0; packed.y = *(unsigned*)&h1;
        packed.z = *(unsigned*)&h2; packed.w = *(unsigned*)&h3;
        *(uint4*)(g_xf_h + (((size_t)n*C + o0 + i)*T + t)*V + v0) = packed;
    }
    g_a[((size_t)n*KK + rr*T + t)*V + vv] = aacc;
    g_b[((size_t)n*KK + rr*T + t)*V + vv] = bacc;
}

// ---------------------------------------------------------------------------
// Kernel 2 (tensor-core): per block: 16v x 16w tile of xm for one n.
// D[64t x 256(vw)] = Wrm[64x128] @ E[128 x 256], E = tanh(a[k,v]-b[k,w]),
// generated on the fly into double-buffered fp16 smem.
// grid (wt=8, vt=8, n=32), 256 threads (8 warps).
// ---------------------------------------------------------------------------
__global__ __launch_bounds__(256, 2) void k2(
    const float* __restrict__ Wrm, const float* __restrict__ brm,
    const float* __restrict__ Ag)
{
    __shared__ float a_s[KK][17];                       // 8.7 KB
    __shared__ __align__(16) __half wrm_s[T][KK];       // 16 KB (swizzled)
    __shared__ __align__(16) __half Et[2][16][256];     // 16 KB (swizzled)
    __shared__ float brm_s[T];

    const int wt = blockIdx.x, vt = blockIdx.y, n = blockIdx.z;
    const int tid = threadIdx.x;
    const int lane = tid & 31, warp = tid >> 5;

    // loads
#pragma unroll
    for (int i = 0; i < 8; i++){
        int idx = i*256 + tid; int k = idx >> 4; int vi = idx & 15;
        a_s[k][vi] = g_a[((size_t)n*KK + k)*V + vt*16 + vi];
    }
#pragma unroll
    for (int i = 0; i < 32; i++){
        int idx = i*256 + tid; int tt = idx >> 7; int kk = idx & 127;
        wrm_s[tt][(kk & 7) + ((((kk >> 3) ^ (tt & 7))) << 3)] =
            __float2half(Wrm[(size_t)tt*KK + kk]);
    }
    if (tid < 64) brm_s[tid] = brm[tid];

    const int r = tid >> 4, wj = tid & 15;      // gen role: k-row r, w-col wj
    float bv[8];
#pragma unroll
    for (int kc = 0; kc < 8; kc++)
        bv[kc] = g_b[((size_t)n*KK + kc*16 + r)*V + wt*16 + wj];

    float acc[4][4][4];
#pragma unroll
    for (int i = 0; i < 4; i++)
#pragma unroll
        for (int j = 0; j < 4; j++)
#pragma unroll
            for (int q = 0; q < 4; q++) acc[i][j][q] = 0.f;

    const unsigned wrm_base = smem_u32(&wrm_s[0][0]);
    const unsigned et_base  = smem_u32(&Et[0][0][0]);

    __syncthreads();

#pragma unroll
    for (int kc = 0; kc < 8; kc++){
        const int buf = kc & 1;
        // --- generate E chunk: Et[r][vi*16+wj] = tanh(a[k][vi]-b[k][wj]) ---
        {
            const float* arow = a_s[kc*16 + r];
            const float bval = bv[kc];
            __half* erow = &Et[buf][r][0];
            const int rsw = r & 7;
#pragma unroll
            for (int vi = 0; vi < 16; vi++){
                float val = tanh_fast(arow[vi] - bval);
                erow[(((vi*2 + (wj >> 3)) ^ rsw) << 3) + (wj & 7)] = __float2half(val);
            }
        }
        __syncthreads();
        // --- mma: A = Wrm chunk, B = E chunk ---
        unsigned afr[4][4];
#pragma unroll
        for (int mt = 0; mt < 4; mt++){
            int row = mt*16 + (lane & 15);
            unsigned addr = wrm_base + row*256 +
                (((kc*2 + (lane >> 4)) ^ (row & 7)) << 4);
            ldm_x4(addr, afr[mt][0], afr[mt][1], afr[mt][2], afr[mt][3]);
        }
        unsigned bfr[4][2];
        {
            int row = lane & 15;
            unsigned rb = et_base + buf*8192 + row*512;
#pragma unroll
            for (int ntl = 0; ntl < 4; ntl++){
                unsigned addr = rb + ((((warp << 2) + ntl) ^ (row & 7)) << 4);
                ldm_x2t(addr, bfr[ntl][0], bfr[ntl][1]);
            }
        }
#pragma unroll
        for (int mt = 0; mt < 4; mt++)
#pragma unroll
            for (int ntl = 0; ntl < 4; ntl++)
                mma16816(acc[mt][ntl], afr[mt], bfr[ntl]);
    }

    // --- epilogue: + brm + A, convert fp16, store xm ---
#pragma unroll
    for (int mt = 0; mt < 4; mt++){
#pragma unroll
        for (int ntl = 0; ntl < 4; ntl++){
            int t0 = mt*16 + (lane >> 2);
            int colbase = (warp << 5) + (ntl << 3) + ((lane & 3) << 1);
            int v   = vt*16 + (colbase >> 4);
            int wgl = wt*16 + (colbase & 15);
#pragma unroll
            for (int h = 0; h < 2; h++){
                int tt = t0 + h*8;
                float2 Av = *(const float2*)&Ag[((size_t)tt*V + v)*V + wgl];
                float r0 = acc[mt][ntl][2*h + 0] + brm_s[tt] + Av.x;
                float r1 = acc[mt][ntl][2*h + 1] + brm_s[tt] + Av.y;
                *(__half2*)&g_xm_h[(((size_t)n*T + tt)*V + v)*V + wgl] =
                    __floats2half2_rn(r0, r1);
            }
        }
    }
}

// ---------------------------------------------------------------------------
// Kernel 3 (tensor-core): per (n,t): out[64c x 128w] = xf[64x128] @ xm[128x128]
// fp16 operands, fp32 out. grid (T, NB), 256 threads (8 warps).
// smem exactly 48 KB (swizzled, no pad).
// ---------------------------------------------------------------------------
__global__ __launch_bounds__(256) void k3(float* __restrict__ out)
{
    __shared__ __align__(16) __half xf_s[C][V];     // 16 KB swizzled
    __shared__ __align__(16) __half xm_s[V][V];     // 32 KB swizzled

    const int t = blockIdx.x, n = blockIdx.y;
    const int tid = threadIdx.x;
    const int lane = tid & 31, warp = tid >> 5;

#pragma unroll
    for (int i = 0; i < 4; i++){
        int idx = i*256 + tid; int c = idx >> 4; int u = idx & 15;
        *(uint4*)&xf_s[c][(u ^ (c & 7)) << 3] =
            *(const uint4*)(g_xf_h + (((size_t)n*C + c)*T + t)*V + u*8);
    }
#pragma unroll
    for (int i = 0; i < 8; i++){
        int idx = i*256 + tid; int v = idx >> 4; int u = idx & 15;
        *(uint4*)&xm_s[v][(u ^ (v & 7)) << 3] =
            *(const uint4*)(g_xm_h + (((size_t)n*T + t)*V + v)*V + u*8);
    }
    __syncthreads();

    const int wm = warp & 1, wn = warp >> 1;
    const unsigned xf_base = smem_u32(&xf_s[0][0]);
    const unsigned xm_base = smem_u32(&xm_s[0][0]);

    float acc[2][4][4];
#pragma unroll
    for (int i = 0; i < 2; i++)
#pragma unroll
        for (int j = 0; j < 4; j++)
#pragma unroll
            for (int q = 0; q < 4; q++) acc[i][j][q] = 0.f;

#pragma unroll
    for (int kc = 0; kc < 8; kc++){
        unsigned afr[2][4];
#pragma unroll
        for (int mtl = 0; mtl < 2; mtl++){
            int row = wm*32 + mtl*16 + (lane & 15);
            unsigned addr = xf_base + row*256 +
                (((kc*2 + (lane >> 4)) ^ (row & 7)) << 4);
            ldm_x4(addr, afr[mtl][0], afr[mtl][1], afr[mtl][2], afr[mtl][3]);
        }
        unsigned bfr[4][2];
        {
            int row = kc*16 + (lane & 15);
            unsigned rb = xm_base + row*256;
#pragma unroll
            for (int ntl = 0; ntl < 4; ntl++){
                unsigned addr = rb + ((((wn << 2) + ntl) ^ (row & 7)) << 4);
                ldm_x2t(addr, bfr[ntl][0], bfr[ntl][1]);
            }
        }
#pragma unroll
        for (int mtl = 0; mtl < 2; mtl++)
#pragma unroll
            for (int ntl = 0; ntl < 4; ntl++)
                mma16816(acc[mtl][ntl], afr[mtl], bfr[ntl]);
    }

#pragma unroll
    for (int mtl = 0; mtl < 2; mtl++){
#pragma unroll
        for (int ntl = 0; ntl < 4; ntl++){
            int c0 = wm*32 + mtl*16 + (lane >> 2);
            int w  = (wn << 5) + (ntl << 3) + ((lane & 3) << 1);
#pragma unroll
            for (int h = 0; h < 2; h++){
                int cc = c0 + h*8;
                *(float2*)(out + (((size_t)n*C + cc)*T + t)*V + w) =
                    make_float2(acc[mtl][ntl][2*h], acc[mtl][ntl][2*h + 1]);
            }
        }
    }
}

extern "C" void kernel_launch(void* const* d_in, const int* in_sizes, int n_in,
                              void* d_out, int out_size)
{
    const float* x   = (const float*)d_in[0];
    const float* A   = (const float*)d_in[1];
    const float* Wf  = (const float*)d_in[2];
    const float* bf  = (const float*)d_in[3];
    const float* Wm1 = (const float*)d_in[4];
    const float* bm1 = (const float*)d_in[5];
    const float* Wm2 = (const float*)d_in[6];
    const float* bm2 = (const float*)d_in[7];
    const float* Wrm = (const float*)d_in[8];
    const float* brm = (const float*)d_in[9];
    float* out = (float*)d_out;

    k1<<<dim3(T, NB), 256>>>(x, Wf, bf, Wm1, bm1, Wm2, bm2);
    k2<<<dim3(8, 8, NB), 256>>>(Wrm, brm, A);
    k3<<<dim3(T, NB), 256>>>(out);
}